// round 9
// baseline (speedup 1.0000x reference)
#include <cuda_runtime.h>
#include <cuda_bf16.h>
#include <math.h>
#include <stdint.h>

// Problem constants
#define B_  2
#define T_  2048
#define D_  2048
#define H_  16
#define DH_ 128
#define M_  4096            // B_*T_

// ---------------- scratch (__device__ globals; no allocs allowed) ----------
__device__ __align__(256) float g_q[8388608];
__device__ __align__(256) float g_k[8388608];
__device__ __align__(256) float g_o[8388608];
__device__ __align__(256) int8_t g_x1[8388608], g_x2[8388608];
__device__ __align__(256) int8_t g_o1[8388608], g_o2[8388608];
__device__ __align__(256) int8_t g_wq1[4194304], g_wq2[4194304];
__device__ __align__(256) int8_t g_wk1[4194304], g_wk2[4194304];
__device__ __align__(256) int8_t g_wv1[4194304], g_wv2[4194304];
__device__ __align__(256) int8_t g_wo1[4194304], g_wo2[4194304];
__device__ float g_sx[4096], g_so[4096];
__device__ float g_swq[2048], g_swk[2048], g_swv[2048], g_swo[2048];
__device__ __align__(256) __nv_bfloat16 g_qh[8388608], g_ql[8388608];
__device__ __align__(256) __nv_bfloat16 g_kh[8388608], g_kl[8388608];
__device__ __align__(256) __nv_bfloat16 g_vh[8388608], g_vl[8388608];

// ---------------- PTX helpers ----------------------------------------------
__device__ __forceinline__ uint32_t smem_u32(const void* p) {
    uint32_t a;
    asm("{ .reg .u64 t; cvta.to.shared.u64 t, %1; cvt.u32.u64 %0, t; }" : "=r"(a) : "l"(p));
    return a;
}
__device__ __forceinline__ void cpa16(uint32_t s, const void* g) {
    asm volatile("cp.async.cg.shared.global [%0], [%1], 16;" :: "r"(s), "l"(g));
}
__device__ __forceinline__ void ldx4(uint32_t* d, uint32_t addr) {
    asm volatile("ldmatrix.sync.aligned.m8n8.x4.shared.b16 {%0,%1,%2,%3}, [%4];"
                 : "=r"(d[0]), "=r"(d[1]), "=r"(d[2]), "=r"(d[3]) : "r"(addr));
}
__device__ __forceinline__ void ldx2(uint32_t* d, uint32_t addr) {
    asm volatile("ldmatrix.sync.aligned.m8n8.x2.shared.b16 {%0,%1}, [%2];"
                 : "=r"(d[0]), "=r"(d[1]) : "r"(addr));
}
__device__ __forceinline__ void ldx2t(uint32_t* d, uint32_t addr) {
    asm volatile("ldmatrix.sync.aligned.m8n8.x2.trans.shared.b16 {%0,%1}, [%2];"
                 : "=r"(d[0]), "=r"(d[1]) : "r"(addr));
}
__device__ __forceinline__ void mma_bf16(float* c, const uint32_t* a, const uint32_t* b) {
    asm volatile(
        "mma.sync.aligned.m16n8k16.row.col.f32.bf16.bf16.f32 "
        "{%0,%1,%2,%3}, {%4,%5,%6,%7}, {%8,%9}, {%0,%1,%2,%3};"
        : "+f"(c[0]), "+f"(c[1]), "+f"(c[2]), "+f"(c[3])
        : "r"(a[0]), "r"(a[1]), "r"(a[2]), "r"(a[3]), "r"(b[0]), "r"(b[1]));
}
__device__ __forceinline__ void mma_s8(int* c, const uint32_t* a, const uint32_t* b) {
    asm volatile(
        "mma.sync.aligned.m16n8k32.row.col.s32.s8.s8.s32 "
        "{%0,%1,%2,%3}, {%4,%5,%6,%7}, {%8,%9}, {%0,%1,%2,%3};"
        : "+r"(c[0]), "+r"(c[1]), "+r"(c[2]), "+r"(c[3])
        : "r"(a[0]), "r"(a[1]), "r"(a[2]), "r"(a[3]), "r"(b[0]), "r"(b[1]));
}
__device__ __forceinline__ uint32_t pk(__nv_bfloat16 a, __nv_bfloat16 b) {
    __nv_bfloat162 t(a, b);
    return *(uint32_t*)&t;
}
__device__ __forceinline__ __nv_bfloat162 split_hi2(float a, float b, __nv_bfloat162& lo) {
    __nv_bfloat16 h0 = __float2bfloat16(a), h1 = __float2bfloat16(b);
    lo = __nv_bfloat162(__float2bfloat16(a - __bfloat162float(h0)),
                        __float2bfloat16(b - __bfloat162float(h1)));
    return __nv_bfloat162(h0, h1);
}
// swizzle for 64-byte rows
__device__ __forceinline__ uint32_t swz(uint32_t off) { return off ^ ((off >> 3) & 0x30); }

// ---------------------------------------------------------------------------
// Per-row 2-limb int8 quantization: x ~= s*(L1 + L2/128), s = rowmax/127.
// One block per row, K elements.
// ---------------------------------------------------------------------------
__global__ __launch_bounds__(256) void quant_rows(
    const float* __restrict__ src, int8_t* __restrict__ L1,
    int8_t* __restrict__ L2, float* __restrict__ scale, int K)
{
    const int row = blockIdx.x;
    const float4* sr = (const float4*)(src + (size_t)row * K);
    const int K4 = K >> 2;

    float mx = 0.f;
    for (int i = threadIdx.x; i < K4; i += 256) {
        float4 v = sr[i];
        mx = fmaxf(mx, fmaxf(fmaxf(fabsf(v.x), fabsf(v.y)), fmaxf(fabsf(v.z), fabsf(v.w))));
    }
#pragma unroll
    for (int o = 16; o > 0; o >>= 1) mx = fmaxf(mx, __shfl_xor_sync(0xffffffffu, mx, o));
    __shared__ float red[8];
    __shared__ float s_s, s_inv;
    if ((threadIdx.x & 31) == 0) red[threadIdx.x >> 5] = mx;
    __syncthreads();
    if (threadIdx.x == 0) {
        float m = 0.f;
        for (int i = 0; i < 8; i++) m = fmaxf(m, red[i]);
        m = fmaxf(m, 1e-30f);
        s_s = m / 127.f;
        s_inv = 127.f / m;
        scale[row] = s_s;
    }
    __syncthreads();
    const float s = s_s, inv = s_inv;
    char4* o1 = (char4*)(L1 + (size_t)row * K);
    char4* o2 = (char4*)(L2 + (size_t)row * K);
    for (int i = threadIdx.x; i < K4; i += 256) {
        float4 v = sr[i];
        int q0 = __float2int_rn(v.x * inv), q1 = __float2int_rn(v.y * inv);
        int q2 = __float2int_rn(v.z * inv), q3 = __float2int_rn(v.w * inv);
        q0 = max(-127, min(127, q0)); q1 = max(-127, min(127, q1));
        q2 = max(-127, min(127, q2)); q3 = max(-127, min(127, q3));
        int r0 = __float2int_rn((v.x - q0 * s) * inv * 128.f);
        int r1 = __float2int_rn((v.y - q1 * s) * inv * 128.f);
        int r2 = __float2int_rn((v.z - q2 * s) * inv * 128.f);
        int r3 = __float2int_rn((v.w - q3 * s) * inv * 128.f);
        r0 = max(-127, min(127, r0)); r1 = max(-127, min(127, r1));
        r2 = max(-127, min(127, r2)); r3 = max(-127, min(127, r3));
        o1[i] = make_char4((char)q0, (char)q1, (char)q2, (char)q3);
        o2[i] = make_char4((char)r0, (char)r1, (char)r2, (char)r3);
    }
}

// ---------------------------------------------------------------------------
// INT8 2-limb GEMM-NT: C[m][n] = sa[m]*sb[n]*(L1a.L1b + (L1a.L2b+L2a.L1b)/128) + bias[n]
// BM=128, BN=128, BK=64. 256 threads = 8 warps (2m x 4n), warp tile 64x32.
// 3 smem stages x 32KB (A1 8K | A2 8K | B1 8K | B2 8K), rows 64B swizzled.
// Output fp32 C (if non-null) and/or bf16 hi/lo split.
// ---------------------------------------------------------------------------
#define QSTAGE 32768
#define QGEMM_SMEM (3 * QSTAGE)

__global__ __launch_bounds__(256, 1) void gemm_s8(
    const int8_t* __restrict__ A1, const int8_t* __restrict__ A2,
    const int8_t* __restrict__ B1, const int8_t* __restrict__ B2,
    const float* __restrict__ sa, const float* __restrict__ sbv,
    const float* __restrict__ bias, float* __restrict__ C,
    __nv_bfloat16* __restrict__ OutH, __nv_bfloat16* __restrict__ OutL,
    int Md, int Nd, int Kd)
{
    extern __shared__ __align__(1024) unsigned char smem[];
    const int tid = threadIdx.x;
    const int wid = tid >> 5;
    const int lane = tid & 31;
    const int wm = wid >> 2;              // 0..1 -> m offset 64*wm
    const int wn = wid & 3;               // 0..3 -> n offset 32*wn
    const int bm = blockIdx.y * 128;
    const int bn = blockIdx.x * 128;
    const uint32_t sbase = smem_u32(smem);
    const int nchunk = Kd >> 6;           // 32

#define QLOAD(stage, k0)                                                        \
    {                                                                            \
        uint32_t sb = sbase + (stage) * QSTAGE;                                  \
        _Pragma("unroll")                                                        \
        for (int j = 0; j < 2; j++) {                                            \
            int idx = tid + j * 256;                                             \
            int r = idx >> 2, c = idx & 3;                                       \
            uint32_t so = swz((uint32_t)(r * 64 + c * 16));                      \
            size_t ga = (size_t)(bm + r) * Kd + (k0) + c * 16;                   \
            size_t gb = (size_t)(bn + r) * Kd + (k0) + c * 16;                   \
            cpa16(sb + so,         A1 + ga);                                     \
            cpa16(sb + 8192 + so,  A2 + ga);                                     \
            cpa16(sb + 16384 + so, B1 + gb);                                     \
            cpa16(sb + 24576 + so, B2 + gb);                                     \
        }                                                                        \
        asm volatile("cp.async.commit_group;" ::: "memory");                     \
    }

    QLOAD(0, 0)
    QLOAD(1, 64)

    int accM[4][4][4], accX[4][4][4];
#pragma unroll
    for (int i = 0; i < 4; i++)
#pragma unroll
        for (int j = 0; j < 4; j++)
#pragma unroll
            for (int l = 0; l < 4; l++) { accM[i][j][l] = 0; accX[i][j][l] = 0; }

    const int arow = lane & 15;
    const int akh = lane >> 4;
    const int brow8 = lane & 7;
    const int bkh = (lane >> 3) & 1;
    const int bni8 = (lane >> 4) & 1;

    for (int i = 0; i < nchunk; i++) {
        if (i + 2 < nchunk) {
            QLOAD((i + 2) % 3, (i + 2) * 64)
            asm volatile("cp.async.wait_group 2;" ::: "memory");
        } else if (i + 1 < nchunk) {
            asm volatile("cp.async.wait_group 1;" ::: "memory");
        } else {
            asm volatile("cp.async.wait_group 0;" ::: "memory");
        }
        __syncthreads();

        const uint32_t sb = sbase + (i % 3) * QSTAGE;
#pragma unroll
        for (int ks = 0; ks < 2; ks++) {   // two k=32 steps (32B each)
            uint32_t a1[4][4], a2[4][4], b1[2][4], b2[2][4];
#pragma unroll
            for (int mi = 0; mi < 4; mi++) {
                uint32_t off = swz((uint32_t)((wm * 64 + mi * 16 + arow) * 64 + ks * 32 + akh * 16));
                ldx4(a1[mi], sb + off);
                ldx4(a2[mi], sb + 8192 + off);
            }
#pragma unroll
            for (int nj = 0; nj < 2; nj++) {
                int r = wn * 32 + nj * 16 + bni8 * 8 + brow8;
                uint32_t off = swz((uint32_t)(r * 64 + ks * 32 + bkh * 16));
                ldx4(b1[nj], sb + 16384 + off);
                ldx4(b2[nj], sb + 24576 + off);
            }
#pragma unroll
            for (int mi = 0; mi < 4; mi++)
#pragma unroll
                for (int nj = 0; nj < 2; nj++) {
                    mma_s8(accM[mi][2 * nj],     a1[mi], &b1[nj][0]);
                    mma_s8(accX[mi][2 * nj],     a1[mi], &b2[nj][0]);
                    mma_s8(accX[mi][2 * nj],     a2[mi], &b1[nj][0]);
                    mma_s8(accM[mi][2 * nj + 1], a1[mi], &b1[nj][2]);
                    mma_s8(accX[mi][2 * nj + 1], a1[mi], &b2[nj][2]);
                    mma_s8(accX[mi][2 * nj + 1], a2[mi], &b1[nj][2]);
                }
        }
        __syncthreads();
    }

    // Epilogue: dequantize + bias
#pragma unroll
    for (int mi = 0; mi < 4; mi++) {
        int r0 = bm + wm * 64 + mi * 16 + (lane >> 2);
        float sA0 = sa[r0], sA1 = sa[r0 + 8];
#pragma unroll
        for (int ni = 0; ni < 4; ni++) {
            int col = bn + wn * 32 + ni * 8 + (lane & 3) * 2;
            float sB0 = sbv[col], sB1 = sbv[col + 1];
            float b0 = bias[col], b1 = bias[col + 1];
            const float inv128 = 0.0078125f;
            float x0 = ((float)accM[mi][ni][0] + (float)accX[mi][ni][0] * inv128) * sA0 * sB0 + b0;
            float x1 = ((float)accM[mi][ni][1] + (float)accX[mi][ni][1] * inv128) * sA0 * sB1 + b1;
            float x2 = ((float)accM[mi][ni][2] + (float)accX[mi][ni][2] * inv128) * sA1 * sB0 + b0;
            float x3 = ((float)accM[mi][ni][3] + (float)accX[mi][ni][3] * inv128) * sA1 * sB1 + b1;
            if (C) {
                *(float2*)(C + (size_t)r0 * Nd + col) = make_float2(x0, x1);
                *(float2*)(C + (size_t)(r0 + 8) * Nd + col) = make_float2(x2, x3);
            }
            if (OutH) {
                __nv_bfloat162 lo0, lo1;
                __nv_bfloat162 h0 = split_hi2(x0, x1, lo0);
                __nv_bfloat162 h1 = split_hi2(x2, x3, lo1);
                *(__nv_bfloat162*)(OutH + (size_t)r0 * Nd + col) = h0;
                *(__nv_bfloat162*)(OutL + (size_t)r0 * Nd + col) = lo0;
                *(__nv_bfloat162*)(OutH + (size_t)(r0 + 8) * Nd + col) = h1;
                *(__nv_bfloat162*)(OutL + (size_t)(r0 + 8) * Nd + col) = lo1;
            }
        }
    }
#undef QLOAD
}

// ---------------------------------------------------------------------------
// Fused RMSNorm + interleaved RoPE -> bf16 hi/lo splits.
// ---------------------------------------------------------------------------
__global__ __launch_bounds__(256) void rmsnorm_rope_split(
    const float* __restrict__ h, const float* __restrict__ w,
    const float* __restrict__ cosb, const float* __restrict__ sinb,
    __nv_bfloat16* __restrict__ outh, __nv_bfloat16* __restrict__ outl)
{
    const int row = blockIdx.x;
    const int t = row & (T_ - 1);
    const float* hr = h + (size_t)row * D_;

    float ss = 0.f;
    for (int i = threadIdx.x; i < D_; i += 256) { float v = hr[i]; ss += v * v; }
#pragma unroll
    for (int o = 16; o > 0; o >>= 1) ss += __shfl_xor_sync(0xffffffffu, ss, o);
    __shared__ float red[8];
    __shared__ float s_inv;
    if ((threadIdx.x & 31) == 0) red[threadIdx.x >> 5] = ss;
    __syncthreads();
    if (threadIdx.x == 0) {
        float s = 0.f;
        for (int i = 0; i < 8; i++) s += red[i];
        s_inv = rsqrtf(s * (1.0f / D_) + 1e-6f);
    }
    __syncthreads();
    const float inv = s_inv;
    const float* ct = cosb + (size_t)t * D_;
    const float* st = sinb + (size_t)t * D_;
    __nv_bfloat162* oh2 = (__nv_bfloat162*)(outh + (size_t)row * D_);
    __nv_bfloat162* ol2 = (__nv_bfloat162*)(outl + (size_t)row * D_);
    for (int i = threadIdx.x; i < D_ / 2; i += 256) {
        int i2 = i * 2;
        float e = hr[i2] * inv * w[i2];
        float o = hr[i2 + 1] * inv * w[i2 + 1];
        float v0 = e * ct[i2]     - o * st[i2];
        float v1 = o * ct[i2 + 1] + e * st[i2 + 1];
        __nv_bfloat162 lo;
        oh2[i] = split_hi2(v0, v1, lo);
        ol2[i] = lo;
    }
}

// ---------------------------------------------------------------------------
// bf16-split mma.sync flash attention (non-causal); fp32 output.
// BM=64 (4 warps x 16 rows), BN=64 per iter, Dh=128. grid=(T/64,H,B), 128 thr.
// ---------------------------------------------------------------------------
#define FA_STAGE 65536

__global__ __launch_bounds__(128, 1) void flash_attn_mma(
    const __nv_bfloat16* __restrict__ Qh, const __nv_bfloat16* __restrict__ Ql,
    const __nv_bfloat16* __restrict__ Kh, const __nv_bfloat16* __restrict__ Kl,
    const __nv_bfloat16* __restrict__ Vh, const __nv_bfloat16* __restrict__ Vl,
    float* __restrict__ O)
{
    extern __shared__ __align__(1024) unsigned char smem[];
    const int tid = threadIdx.x;
    const int wid = tid >> 5, lane = tid & 31;
    const int b = blockIdx.z, h = blockIdx.y;
    const int q0 = blockIdx.x * 64;
    const uint32_t sbase = smem_u32(smem);
    const size_t rowbase = ((size_t)b * T_) * D_ + h * DH_;

#define LOADKV(it_, stg)                                                         \
    {                                                                            \
        uint32_t sb_ = sbase + (stg) * FA_STAGE;                                 \
        size_t base_ = rowbase + (size_t)((it_) * 64) * D_;                      \
        for (int t = tid; t < 1024; t += 128) {                                  \
            int r_ = t >> 4, c_ = t & 15;                                        \
            uint32_t ph_ = r_ * 256 + ((c_ ^ (r_ & 7)) << 4);                    \
            size_t g_ = base_ + (size_t)r_ * D_ + c_ * 8;                        \
            cpa16(sb_ + ph_,          Kh + g_);                                  \
            cpa16(sb_ + 16384 + ph_,  Kl + g_);                                  \
            cpa16(sb_ + 32768 + ph_,  Vh + g_);                                  \
            cpa16(sb_ + 49152 + ph_,  Vl + g_);                                  \
        }                                                                        \
        asm volatile("cp.async.commit_group;" ::: "memory");                     \
    }

    for (int t = tid; t < 1024; t += 128) {
        int r = t >> 4, c = t & 15;
        uint32_t ph = r * 256 + ((c ^ (r & 7)) << 4);
        size_t g = rowbase + (size_t)(q0 + r) * D_ + c * 8;
        cpa16(sbase + ph, Qh + g);
        cpa16(sbase + 16384 + ph, Ql + g);
    }
    asm volatile("cp.async.commit_group;" ::: "memory");
    asm volatile("cp.async.wait_group 0;" ::: "memory");
    __syncthreads();

    uint32_t qh[8][4], ql[8][4];
    {
        int r = wid * 16 + (lane & 15);
        int khalf = lane >> 4;
#pragma unroll
        for (int kk = 0; kk < 8; kk++) {
            int chunk = kk * 2 + khalf;
            uint32_t ph = r * 256 + ((chunk ^ (r & 7)) << 4);
            ldx4(qh[kk], sbase + ph);
            ldx4(ql[kk], sbase + 16384 + ph);
        }
    }
    __syncthreads();

    float o[16][4];
#pragma unroll
    for (int i = 0; i < 16; i++)
#pragma unroll
        for (int j = 0; j < 4; j++) o[i][j] = 0.f;
    float m0 = -1e30f, m1 = -1e30f, l0 = 0.f, l1 = 0.f;

    LOADKV(0, 0)
    LOADKV(1, 1)

    const float scale = 0.08838834764831845f;
    const int NIT = T_ / 64;

    for (int it = 0; it < NIT; it++) {
        if (it < NIT - 1) { asm volatile("cp.async.wait_group 1;" ::: "memory"); }
        else              { asm volatile("cp.async.wait_group 0;" ::: "memory"); }
        __syncthreads();
        const uint32_t sb = sbase + (it & 1) * FA_STAGE;

        float s[8][4];
#pragma unroll
        for (int n = 0; n < 8; n++)
#pragma unroll
            for (int j = 0; j < 4; j++) s[n][j] = 0.f;

        const int krow_lo = lane & 7;
        const int kkh = ((lane & 15) >> 3) & 1;
#pragma unroll
        for (int kk = 0; kk < 8; kk++) {
#pragma unroll
            for (int n = 0; n < 8; n++) {
                int r = n * 8 + krow_lo;
                int chunk = kk * 2 + kkh;
                uint32_t ph = r * 256 + ((chunk ^ (r & 7)) << 4);
                uint32_t bh[2], bl[2];
                ldx2(bh, sb + ph);
                ldx2(bl, sb + 16384 + ph);
                mma_bf16(s[n], qh[kk], bh);
                mma_bf16(s[n], qh[kk], bl);
                mma_bf16(s[n], ql[kk], bh);
            }
        }

#pragma unroll
        for (int n = 0; n < 8; n++)
#pragma unroll
            for (int j = 0; j < 4; j++) s[n][j] *= scale;

        float cm0 = -1e30f, cm1 = -1e30f;
#pragma unroll
        for (int n = 0; n < 8; n++) {
            cm0 = fmaxf(cm0, fmaxf(s[n][0], s[n][1]));
            cm1 = fmaxf(cm1, fmaxf(s[n][2], s[n][3]));
        }
        cm0 = fmaxf(cm0, __shfl_xor_sync(0xffffffffu, cm0, 1));
        cm0 = fmaxf(cm0, __shfl_xor_sync(0xffffffffu, cm0, 2));
        cm1 = fmaxf(cm1, __shfl_xor_sync(0xffffffffu, cm1, 1));
        cm1 = fmaxf(cm1, __shfl_xor_sync(0xffffffffu, cm1, 2));
        float mn0 = fmaxf(m0, cm0), mn1 = fmaxf(m1, cm1);
        float a0 = __expf(m0 - mn0), a1 = __expf(m1 - mn1);
        float sum0 = 0.f, sum1 = 0.f;
#pragma unroll
        for (int n = 0; n < 8; n++) {
            s[n][0] = __expf(s[n][0] - mn0);
            s[n][1] = __expf(s[n][1] - mn0);
            s[n][2] = __expf(s[n][2] - mn1);
            s[n][3] = __expf(s[n][3] - mn1);
            sum0 += s[n][0] + s[n][1];
            sum1 += s[n][2] + s[n][3];
        }
        sum0 += __shfl_xor_sync(0xffffffffu, sum0, 1);
        sum0 += __shfl_xor_sync(0xffffffffu, sum0, 2);
        sum1 += __shfl_xor_sync(0xffffffffu, sum1, 1);
        sum1 += __shfl_xor_sync(0xffffffffu, sum1, 2);
        l0 = l0 * a0 + sum0;
        l1 = l1 * a1 + sum1;
        m0 = mn0; m1 = mn1;
#pragma unroll
        for (int ni = 0; ni < 16; ni++) {
            o[ni][0] *= a0; o[ni][1] *= a0;
            o[ni][2] *= a1; o[ni][3] *= a1;
        }

        const int vrow = lane & 15;
#pragma unroll
        for (int j = 0; j < 4; j++) {
            uint32_t pa[4], pb[4];
#pragma unroll
            for (int half = 0; half < 2; half++) {
                float x0 = s[2 * j + half][0], x1 = s[2 * j + half][1];
                float x2 = s[2 * j + half][2], x3 = s[2 * j + half][3];
                __nv_bfloat16 h0 = __float2bfloat16(x0), h1 = __float2bfloat16(x1);
                __nv_bfloat16 h2 = __float2bfloat16(x2), h3 = __float2bfloat16(x3);
                pa[2 * half]     = pk(h0, h1);
                pa[2 * half + 1] = pk(h2, h3);
                pb[2 * half]     = pk(__float2bfloat16(x0 - __bfloat162float(h0)),
                                      __float2bfloat16(x1 - __bfloat162float(h1)));
                pb[2 * half + 1] = pk(__float2bfloat16(x2 - __bfloat162float(h2)),
                                      __float2bfloat16(x3 - __bfloat162float(h3)));
            }
            int r = j * 16 + vrow;
#pragma unroll
            for (int ni = 0; ni < 16; ni++) {
                uint32_t ph = r * 256 + ((ni ^ (r & 7)) << 4);
                uint32_t vh[2], vl[2];
                ldx2t(vh, sb + 32768 + ph);
                ldx2t(vl, sb + 49152 + ph);
                mma_bf16(o[ni], pa, vh);
                mma_bf16(o[ni], pa, vl);
                mma_bf16(o[ni], pb, vh);
            }
        }
        __syncthreads();
        if (it + 2 < NIT) { LOADKV(it + 2, it & 1) }
    }

    float i0 = 1.f / l0, i1 = 1.f / l1;
    int r_lo = q0 + wid * 16 + (lane >> 2);
#pragma unroll
    for (int ni = 0; ni < 16; ni++) {
        int col = ni * 8 + (lane & 3) * 2;
        float2 v0 = make_float2(o[ni][0] * i0, o[ni][1] * i0);
        float2 v1 = make_float2(o[ni][2] * i1, o[ni][3] * i1);
        *(float2*)(O + rowbase + (size_t)r_lo * D_ + col) = v0;
        *(float2*)(O + rowbase + (size_t)(r_lo + 8) * D_ + col) = v1;
    }
#undef LOADKV
}

// ---------------------------------------------------------------------------
// Launch
// ---------------------------------------------------------------------------
extern "C" void kernel_launch(void* const* d_in, const int* in_sizes, int n_in,
                              void* d_out, int out_size)
{
    const float* x    = (const float*)d_in[0];
    const float* cosb = (const float*)d_in[1];
    const float* sinb = (const float*)d_in[2];
    const float* Wq   = (const float*)d_in[3];
    const float* bq   = (const float*)d_in[4];
    const float* Wk   = (const float*)d_in[5];
    const float* bk   = (const float*)d_in[6];
    const float* Wv   = (const float*)d_in[7];
    const float* bv   = (const float*)d_in[8];
    const float* qnw  = (const float*)d_in[9];
    const float* knw  = (const float*)d_in[10];
    const float* Wo   = (const float*)d_in[11];
    const float* bo   = (const float*)d_in[12];
    float* out = (float*)d_out;

    float *qp, *kp, *op;
    cudaGetSymbolAddress((void**)&qp, g_q);
    cudaGetSymbolAddress((void**)&kp, g_k);
    cudaGetSymbolAddress((void**)&op, g_o);
    int8_t *x1, *x2, *o1, *o2, *wq1, *wq2, *wk1, *wk2, *wv1, *wv2, *wo1, *wo2;
    cudaGetSymbolAddress((void**)&x1, g_x1);   cudaGetSymbolAddress((void**)&x2, g_x2);
    cudaGetSymbolAddress((void**)&o1, g_o1);   cudaGetSymbolAddress((void**)&o2, g_o2);
    cudaGetSymbolAddress((void**)&wq1, g_wq1); cudaGetSymbolAddress((void**)&wq2, g_wq2);
    cudaGetSymbolAddress((void**)&wk1, g_wk1); cudaGetSymbolAddress((void**)&wk2, g_wk2);
    cudaGetSymbolAddress((void**)&wv1, g_wv1); cudaGetSymbolAddress((void**)&wv2, g_wv2);
    cudaGetSymbolAddress((void**)&wo1, g_wo1); cudaGetSymbolAddress((void**)&wo2, g_wo2);
    float *sx, *so, *swq, *swk, *swv, *swo;
    cudaGetSymbolAddress((void**)&sx, g_sx);   cudaGetSymbolAddress((void**)&so, g_so);
    cudaGetSymbolAddress((void**)&swq, g_swq); cudaGetSymbolAddress((void**)&swk, g_swk);
    cudaGetSymbolAddress((void**)&swv, g_swv); cudaGetSymbolAddress((void**)&swo, g_swo);
    __nv_bfloat16 *qhp, *qlp, *khp, *klp, *vhp, *vlp;
    cudaGetSymbolAddress((void**)&qhp, g_qh);  cudaGetSymbolAddress((void**)&qlp, g_ql);
    cudaGetSymbolAddress((void**)&khp, g_kh);  cudaGetSymbolAddress((void**)&klp, g_kl);
    cudaGetSymbolAddress((void**)&vhp, g_vh);  cudaGetSymbolAddress((void**)&vlp, g_vl);

    // quantize inputs
    quant_rows<<<M_, 256>>>(x, x1, x2, sx, D_);
    quant_rows<<<D_, 256>>>(Wq, wq1, wq2, swq, D_);
    quant_rows<<<D_, 256>>>(Wk, wk1, wk2, swk, D_);
    quant_rows<<<D_, 256>>>(Wv, wv1, wv2, swv, D_);
    quant_rows<<<D_, 256>>>(Wo, wo1, wo2, swo, D_);

    cudaFuncSetAttribute(gemm_s8, cudaFuncAttributeMaxDynamicSharedMemorySize, QGEMM_SMEM);
    dim3 qgrid(D_ / 128, M_ / 128);   // (16, 32)
    gemm_s8<<<qgrid, 256, QGEMM_SMEM>>>(x1, x2, wq1, wq2, sx, swq, bq, qp, nullptr, nullptr, M_, D_, D_);
    gemm_s8<<<qgrid, 256, QGEMM_SMEM>>>(x1, x2, wk1, wk2, sx, swk, bk, kp, nullptr, nullptr, M_, D_, D_);
    gemm_s8<<<qgrid, 256, QGEMM_SMEM>>>(x1, x2, wv1, wv2, sx, swv, bv, nullptr, vhp, vlp, M_, D_, D_);

    rmsnorm_rope_split<<<M_, 256>>>(qp, qnw, cosb, sinb, qhp, qlp);
    rmsnorm_rope_split<<<M_, 256>>>(kp, knw, cosb, sinb, khp, klp);

    cudaFuncSetAttribute(flash_attn_mma, cudaFuncAttributeMaxDynamicSharedMemorySize, 2 * FA_STAGE);
    flash_attn_mma<<<dim3(T_ / 64, H_, B_), 128, 2 * FA_STAGE>>>(qhp, qlp, khp, klp, vhp, vlp, op);

    quant_rows<<<M_, 256>>>(op, o1, o2, so, D_);
    gemm_s8<<<qgrid, 256, QGEMM_SMEM>>>(o1, o2, wo1, wo2, so, swo, bo, out, nullptr, nullptr, M_, D_, D_);
}

// round 11
// speedup vs baseline: 3.2846x; 3.2846x over previous
#include <cuda_runtime.h>
#include <cuda_fp16.h>
#include <math.h>
#include <stdint.h>

// Problem constants
#define B_  2
#define T_  2048
#define D_  2048
#define H_  16
#define DH_ 128
#define M_  4096            // B_*T_

// ---------------- scratch (__device__ globals; no allocs allowed) ----------
__device__ __align__(256) float g_q[8388608];
__device__ __align__(256) float g_k[8388608];
__device__ __align__(256) __half g_xh[8388608], g_xl[8388608];
__device__ __align__(256) __half g_qh[8388608], g_ql[8388608];
__device__ __align__(256) __half g_k16[8388608];
__device__ __align__(256) __half g_v16[8388608];
__device__ __align__(256) __half g_oh[8388608], g_ol[8388608];
__device__ __align__(256) __half g_wq16[4194304], g_wk16[4194304];
__device__ __align__(256) __half g_wv16[4194304], g_wo16[4194304];

// ---------------- PTX helpers ----------------------------------------------
__device__ __forceinline__ uint32_t smem_u32(const void* p) {
    uint32_t a;
    asm("{ .reg .u64 t; cvta.to.shared.u64 t, %1; cvt.u32.u64 %0, t; }" : "=r"(a) : "l"(p));
    return a;
}
__device__ __forceinline__ void cpa16(uint32_t s, const void* g) {
    asm volatile("cp.async.cg.shared.global [%0], [%1], 16;" :: "r"(s), "l"(g));
}
__device__ __forceinline__ void ldx4(uint32_t* d, uint32_t addr) {
    asm volatile("ldmatrix.sync.aligned.m8n8.x4.shared.b16 {%0,%1,%2,%3}, [%4];"
                 : "=r"(d[0]), "=r"(d[1]), "=r"(d[2]), "=r"(d[3]) : "r"(addr));
}
__device__ __forceinline__ void ldx2(uint32_t* d, uint32_t addr) {
    asm volatile("ldmatrix.sync.aligned.m8n8.x2.shared.b16 {%0,%1}, [%2];"
                 : "=r"(d[0]), "=r"(d[1]) : "r"(addr));
}
__device__ __forceinline__ void ldx2t(uint32_t* d, uint32_t addr) {
    asm volatile("ldmatrix.sync.aligned.m8n8.x2.trans.shared.b16 {%0,%1}, [%2];"
                 : "=r"(d[0]), "=r"(d[1]) : "r"(addr));
}
__device__ __forceinline__ void mma_f16(float* c, const uint32_t* a, const uint32_t* b) {
    asm volatile(
        "mma.sync.aligned.m16n8k16.row.col.f32.f16.f16.f32 "
        "{%0,%1,%2,%3}, {%4,%5,%6,%7}, {%8,%9}, {%0,%1,%2,%3};"
        : "+f"(c[0]), "+f"(c[1]), "+f"(c[2]), "+f"(c[3])
        : "r"(a[0]), "r"(a[1]), "r"(a[2]), "r"(a[3]), "r"(b[0]), "r"(b[1]));
}
__device__ __forceinline__ uint32_t pkh(__half a, __half b) {
    __half2 t = __halves2half2(a, b);
    return *(uint32_t*)&t;
}
__device__ __forceinline__ __half2 split_h2(float a, float b, __half2& lo) {
    __half h0 = __float2half_rn(a), h1 = __float2half_rn(b);
    lo = __halves2half2(__float2half_rn(a - __half2float(h0)),
                        __float2half_rn(b - __half2float(h1)));
    return __halves2half2(h0, h1);
}
// swizzle for 64-byte rows
__device__ __forceinline__ uint32_t swz(uint32_t off) { return off ^ ((off >> 3) & 0x30); }

// ---------------------------------------------------------------------------
// fp16 2-pass GEMM-NT: C[m][n] = sum_k (Ah+Al)[m][k]*Bf[n][k] + bias[n]
// BM=128, BN=256, BK=32. 256 threads = 8 warps (2m x 4n), warp tile 64x64.
// 3 smem stages x 32KB (Ah 8K | Al 8K | B 16K). Output fp32 C and/or fp16.
// ---------------------------------------------------------------------------
#define GSTAGE 32768
#define GEMM_SMEM (3 * GSTAGE)

__global__ __launch_bounds__(256, 1) void gemm_f16_2p(
    const __half* __restrict__ Ah, const __half* __restrict__ Al,
    const __half* __restrict__ Bf,
    const float* __restrict__ bias, float* __restrict__ C,
    __half* __restrict__ OutF,
    int Md, int Nd, int Kd)
{
    extern __shared__ __align__(1024) unsigned char smem[];
    const int tid = threadIdx.x;
    const int wid = tid >> 5;
    const int lane = tid & 31;
    const int wm = wid >> 2;              // 0..1
    const int wn = wid & 3;               // 0..3
    const int bm = blockIdx.y * 128;
    const int bn = blockIdx.x * 256;
    const uint32_t sbase = smem_u32(smem);
    const int nchunk = Kd >> 5;           // 64

#define LOAD_STAGE(stage, k0)                                                   \
    {                                                                            \
        uint32_t sb = sbase + (stage) * GSTAGE;                                  \
        _Pragma("unroll")                                                        \
        for (int j = 0; j < 2; j++) {                                            \
            int idx = tid + j * 256;                                             \
            int r = idx >> 2, c = idx & 3;                                       \
            uint32_t so = swz((uint32_t)(r * 64 + c * 16));                      \
            size_t ga = (size_t)(bm + r) * Kd + (k0) + c * 8;                    \
            cpa16(sb + so,        Ah + ga);                                      \
            cpa16(sb + 8192 + so, Al + ga);                                      \
        }                                                                        \
        _Pragma("unroll")                                                        \
        for (int j = 0; j < 4; j++) {                                            \
            int idx = tid + j * 256;                                             \
            int r = idx >> 2, c = idx & 3;                                       \
            uint32_t so = swz((uint32_t)(r * 64 + c * 16));                      \
            size_t gb = (size_t)(bn + r) * Kd + (k0) + c * 8;                    \
            cpa16(sb + 16384 + so, Bf + gb);                                     \
        }                                                                        \
        asm volatile("cp.async.commit_group;" ::: "memory");                     \
    }

    LOAD_STAGE(0, 0)
    LOAD_STAGE(1, 32)

    float acc[4][8][4];
#pragma unroll
    for (int i = 0; i < 4; i++)
#pragma unroll
        for (int j = 0; j < 8; j++)
#pragma unroll
            for (int l = 0; l < 4; l++) acc[i][j][l] = 0.f;

    const int arow = lane & 15;
    const int akh = lane >> 4;
    const int brow8 = lane & 7;
    const int bkh = (lane >> 3) & 1;
    const int bni8 = (lane >> 4) & 1;

    for (int i = 0; i < nchunk; i++) {
        if (i + 2 < nchunk) {
            LOAD_STAGE((i + 2) % 3, (i + 2) * 32)
            asm volatile("cp.async.wait_group 2;" ::: "memory");
        } else if (i + 1 < nchunk) {
            asm volatile("cp.async.wait_group 1;" ::: "memory");
        } else {
            asm volatile("cp.async.wait_group 0;" ::: "memory");
        }
        __syncthreads();

        const uint32_t sb = sbase + (i % 3) * GSTAGE;
#pragma unroll
        for (int ks = 0; ks < 2; ks++) {
            uint32_t ah[4][4], al[4][4], bf[4][4];
#pragma unroll
            for (int mi = 0; mi < 4; mi++) {
                uint32_t off = swz((uint32_t)((wm * 64 + mi * 16 + arow) * 64 + ks * 32 + akh * 16));
                ldx4(ah[mi], sb + off);
                ldx4(al[mi], sb + 8192 + off);
            }
#pragma unroll
            for (int nj = 0; nj < 4; nj++) {
                int r = wn * 64 + nj * 16 + bni8 * 8 + brow8;
                uint32_t off = swz((uint32_t)(r * 64 + ks * 32 + bkh * 16));
                ldx4(bf[nj], sb + 16384 + off);
            }
#pragma unroll
            for (int mi = 0; mi < 4; mi++)
#pragma unroll
                for (int nj = 0; nj < 4; nj++) {
                    mma_f16(acc[mi][2 * nj],     ah[mi], &bf[nj][0]);
                    mma_f16(acc[mi][2 * nj],     al[mi], &bf[nj][0]);
                    mma_f16(acc[mi][2 * nj + 1], ah[mi], &bf[nj][2]);
                    mma_f16(acc[mi][2 * nj + 1], al[mi], &bf[nj][2]);
                }
        }
        __syncthreads();
    }

    // Epilogue
#pragma unroll
    for (int mi = 0; mi < 4; mi++) {
        int r0 = bm + wm * 64 + mi * 16 + (lane >> 2);
#pragma unroll
        for (int ni = 0; ni < 8; ni++) {
            int col = bn + wn * 64 + ni * 8 + (lane & 3) * 2;
            float b0 = bias[col], b1 = bias[col + 1];
            float x0 = acc[mi][ni][0] + b0, x1 = acc[mi][ni][1] + b1;
            float x2 = acc[mi][ni][2] + b0, x3 = acc[mi][ni][3] + b1;
            if (C) {
                *(float2*)(C + (size_t)r0 * Nd + col) = make_float2(x0, x1);
                *(float2*)(C + (size_t)(r0 + 8) * Nd + col) = make_float2(x2, x3);
            }
            if (OutF) {
                *(__half2*)(OutF + (size_t)r0 * Nd + col) = __floats2half2_rn(x0, x1);
                *(__half2*)(OutF + (size_t)(r0 + 8) * Nd + col) = __floats2half2_rn(x2, x3);
            }
        }
    }
#undef LOAD_STAGE
}

// ---------------------------------------------------------------------------
// fp32 -> fp16 hi/lo split (lo optional: pass nullptr for single-fp16 convert)
// ---------------------------------------------------------------------------
__global__ __launch_bounds__(256) void split_f16(
    const float4* __restrict__ src, __half2* __restrict__ hi,
    __half2* __restrict__ lo, int n4)
{
    int i = blockIdx.x * 256 + threadIdx.x;
    if (i >= n4) return;
    float4 v = src[i];
    __half2 l0, l1;
    __half2 h0 = split_h2(v.x, v.y, l0);
    __half2 h1 = split_h2(v.z, v.w, l1);
    hi[2 * i] = h0; hi[2 * i + 1] = h1;
    if (lo) { lo[2 * i] = l0; lo[2 * i + 1] = l1; }
}

// ---------------------------------------------------------------------------
// Fused RMSNorm + interleaved RoPE -> fp16 hi (+ optional lo split).
// ---------------------------------------------------------------------------
__global__ __launch_bounds__(256) void rmsnorm_rope_f16(
    const float* __restrict__ h, const float* __restrict__ w,
    const float* __restrict__ cosb, const float* __restrict__ sinb,
    __half* __restrict__ outh, __half* __restrict__ outl)
{
    const int row = blockIdx.x;
    const int t = row & (T_ - 1);
    const float* hr = h + (size_t)row * D_;

    float ss = 0.f;
    for (int i = threadIdx.x; i < D_; i += 256) { float v = hr[i]; ss += v * v; }
#pragma unroll
    for (int o = 16; o > 0; o >>= 1) ss += __shfl_xor_sync(0xffffffffu, ss, o);
    __shared__ float red[8];
    __shared__ float s_inv;
    if ((threadIdx.x & 31) == 0) red[threadIdx.x >> 5] = ss;
    __syncthreads();
    if (threadIdx.x == 0) {
        float s = 0.f;
        for (int i = 0; i < 8; i++) s += red[i];
        s_inv = rsqrtf(s * (1.0f / D_) + 1e-6f);
    }
    __syncthreads();
    const float inv = s_inv;
    const float* ct = cosb + (size_t)t * D_;
    const float* st = sinb + (size_t)t * D_;
    __half2* oh2 = (__half2*)(outh + (size_t)row * D_);
    __half2* ol2 = outl ? (__half2*)(outl + (size_t)row * D_) : nullptr;
    for (int i = threadIdx.x; i < D_ / 2; i += 256) {
        int i2 = i * 2;
        float e = hr[i2] * inv * w[i2];
        float o = hr[i2 + 1] * inv * w[i2 + 1];
        float v0 = e * ct[i2]     - o * st[i2];
        float v1 = o * ct[i2 + 1] + e * st[i2 + 1];
        __half2 lo;
        __half2 hi = split_h2(v0, v1, lo);
        oh2[i] = hi;
        if (ol2) ol2[i] = lo;
    }
}

// ---------------------------------------------------------------------------
// fp16 2-pass mma.sync flash attention (non-causal); output fp16 hi/lo split.
// Q split (hi+lo frags), K single, V single (P split in-register).
// BM=64 (4 warps x 16 rows), BN=64 per iter, Dh=128. grid=(T/64,H,B), 128 thr.
// smem: 2 stages x (K 16K | V 16K) = 64KB. Q staged in stage0 region first.
// ---------------------------------------------------------------------------
#define FA_STAGE 32768

__global__ __launch_bounds__(128, 1) void flash_attn_f16(
    const __half* __restrict__ Qh, const __half* __restrict__ Ql,
    const __half* __restrict__ Kf, const __half* __restrict__ Vf,
    __half* __restrict__ Oh, __half* __restrict__ Ol)
{
    extern __shared__ __align__(1024) unsigned char smem[];
    const int tid = threadIdx.x;
    const int wid = tid >> 5, lane = tid & 31;
    const int b = blockIdx.z, h = blockIdx.y;
    const int q0 = blockIdx.x * 64;
    const uint32_t sbase = smem_u32(smem);
    const size_t rowbase = ((size_t)b * T_) * D_ + h * DH_;

#define LOADKV(it_, stg)                                                         \
    {                                                                            \
        uint32_t sb_ = sbase + (stg) * FA_STAGE;                                 \
        size_t base_ = rowbase + (size_t)((it_) * 64) * D_;                      \
        for (int t = tid; t < 1024; t += 128) {                                  \
            int r_ = t >> 4, c_ = t & 15;                                        \
            uint32_t ph_ = r_ * 256 + ((c_ ^ (r_ & 7)) << 4);                    \
            size_t g_ = base_ + (size_t)r_ * D_ + c_ * 8;                        \
            cpa16(sb_ + ph_,          Kf + g_);                                  \
            cpa16(sb_ + 16384 + ph_,  Vf + g_);                                  \
        }                                                                        \
        asm volatile("cp.async.commit_group;" ::: "memory");                     \
    }

    // stage Q (hi at 0, lo at +16K in stage0 region), build fragments
    for (int t = tid; t < 1024; t += 128) {
        int r = t >> 4, c = t & 15;
        uint32_t ph = r * 256 + ((c ^ (r & 7)) << 4);
        size_t g = rowbase + (size_t)(q0 + r) * D_ + c * 8;
        cpa16(sbase + ph, Qh + g);
        cpa16(sbase + 16384 + ph, Ql + g);
    }
    asm volatile("cp.async.commit_group;" ::: "memory");
    asm volatile("cp.async.wait_group 0;" ::: "memory");
    __syncthreads();

    uint32_t qh[8][4], ql[8][4];
    {
        int r = wid * 16 + (lane & 15);
        int khalf = lane >> 4;
#pragma unroll
        for (int kk = 0; kk < 8; kk++) {
            int chunk = kk * 2 + khalf;
            uint32_t ph = r * 256 + ((chunk ^ (r & 7)) << 4);
            ldx4(qh[kk], sbase + ph);
            ldx4(ql[kk], sbase + 16384 + ph);
        }
    }
    __syncthreads();

    float o[16][4];
#pragma unroll
    for (int i = 0; i < 16; i++)
#pragma unroll
        for (int j = 0; j < 4; j++) o[i][j] = 0.f;
    float m0 = -1e30f, m1 = -1e30f, l0 = 0.f, l1 = 0.f;

    LOADKV(0, 0)
    LOADKV(1, 1)

    const float scale = 0.08838834764831845f;
    const int NIT = T_ / 64;

    for (int it = 0; it < NIT; it++) {
        if (it < NIT - 1) { asm volatile("cp.async.wait_group 1;" ::: "memory"); }
        else              { asm volatile("cp.async.wait_group 0;" ::: "memory"); }
        __syncthreads();
        const uint32_t sb = sbase + (it & 1) * FA_STAGE;

        // ---- S = (Qh+Ql) K^T ----
        float s[8][4];
#pragma unroll
        for (int n = 0; n < 8; n++)
#pragma unroll
            for (int j = 0; j < 4; j++) s[n][j] = 0.f;

        const int krow_lo = lane & 7;
        const int kkh = ((lane & 15) >> 3) & 1;
#pragma unroll
        for (int kk = 0; kk < 8; kk++) {
#pragma unroll
            for (int n = 0; n < 8; n++) {
                int r = n * 8 + krow_lo;
                int chunk = kk * 2 + kkh;
                uint32_t ph = r * 256 + ((chunk ^ (r & 7)) << 4);
                uint32_t bh[2];
                ldx2(bh, sb + ph);
                mma_f16(s[n], qh[kk], bh);
                mma_f16(s[n], ql[kk], bh);
            }
        }

#pragma unroll
        for (int n = 0; n < 8; n++)
#pragma unroll
            for (int j = 0; j < 4; j++) s[n][j] *= scale;

        // ---- online softmax ----
        float cm0 = -1e30f, cm1 = -1e30f;
#pragma unroll
        for (int n = 0; n < 8; n++) {
            cm0 = fmaxf(cm0, fmaxf(s[n][0], s[n][1]));
            cm1 = fmaxf(cm1, fmaxf(s[n][2], s[n][3]));
        }
        cm0 = fmaxf(cm0, __shfl_xor_sync(0xffffffffu, cm0, 1));
        cm0 = fmaxf(cm0, __shfl_xor_sync(0xffffffffu, cm0, 2));
        cm1 = fmaxf(cm1, __shfl_xor_sync(0xffffffffu, cm1, 1));
        cm1 = fmaxf(cm1, __shfl_xor_sync(0xffffffffu, cm1, 2));
        float mn0 = fmaxf(m0, cm0), mn1 = fmaxf(m1, cm1);
        float a0 = __expf(m0 - mn0), a1 = __expf(m1 - mn1);
        float sum0 = 0.f, sum1 = 0.f;
#pragma unroll
        for (int n = 0; n < 8; n++) {
            s[n][0] = __expf(s[n][0] - mn0);
            s[n][1] = __expf(s[n][1] - mn0);
            s[n][2] = __expf(s[n][2] - mn1);
            s[n][3] = __expf(s[n][3] - mn1);
            sum0 += s[n][0] + s[n][1];
            sum1 += s[n][2] + s[n][3];
        }
        sum0 += __shfl_xor_sync(0xffffffffu, sum0, 1);
        sum0 += __shfl_xor_sync(0xffffffffu, sum0, 2);
        sum1 += __shfl_xor_sync(0xffffffffu, sum1, 1);
        sum1 += __shfl_xor_sync(0xffffffffu, sum1, 2);
        l0 = l0 * a0 + sum0;
        l1 = l1 * a1 + sum1;
        m0 = mn0; m1 = mn1;
#pragma unroll
        for (int ni = 0; ni < 16; ni++) {
            o[ni][0] *= a0; o[ni][1] *= a0;
            o[ni][2] *= a1; o[ni][3] *= a1;
        }

        // ---- O += (Ph+Pl) V ----
        const int vrow = lane & 15;
#pragma unroll
        for (int j = 0; j < 4; j++) {
            uint32_t pa[4], pb[4];
#pragma unroll
            for (int half = 0; half < 2; half++) {
                float x0 = s[2 * j + half][0], x1 = s[2 * j + half][1];
                float x2 = s[2 * j + half][2], x3 = s[2 * j + half][3];
                __half h0 = __float2half_rn(x0), h1 = __float2half_rn(x1);
                __half h2 = __float2half_rn(x2), h3 = __float2half_rn(x3);
                pa[2 * half]     = pkh(h0, h1);
                pa[2 * half + 1] = pkh(h2, h3);
                pb[2 * half]     = pkh(__float2half_rn(x0 - __half2float(h0)),
                                       __float2half_rn(x1 - __half2float(h1)));
                pb[2 * half + 1] = pkh(__float2half_rn(x2 - __half2float(h2)),
                                       __float2half_rn(x3 - __half2float(h3)));
            }
            int r = j * 16 + vrow;
#pragma unroll
            for (int ni = 0; ni < 16; ni++) {
                uint32_t ph = r * 256 + ((ni ^ (r & 7)) << 4);
                uint32_t vh[2];
                ldx2t(vh, sb + 16384 + ph);
                mma_f16(o[ni], pa, vh);
                mma_f16(o[ni], pb, vh);
            }
        }
        __syncthreads();
        if (it + 2 < NIT) { LOADKV(it + 2, it & 1) }
    }

    // ---- store as fp16 hi/lo split ----
    float i0 = 1.f / l0, i1 = 1.f / l1;
    int r_lo = q0 + wid * 16 + (lane >> 2);
#pragma unroll
    for (int ni = 0; ni < 16; ni++) {
        int col = ni * 8 + (lane & 3) * 2;
        size_t idx0 = rowbase + (size_t)r_lo * D_ + col;
        size_t idx1 = rowbase + (size_t)(r_lo + 8) * D_ + col;
        __half2 lo0, lo1;
        __half2 h0 = split_h2(o[ni][0] * i0, o[ni][1] * i0, lo0);
        __half2 h1 = split_h2(o[ni][2] * i1, o[ni][3] * i1, lo1);
        *(__half2*)(Oh + idx0) = h0;
        *(__half2*)(Ol + idx0) = lo0;
        *(__half2*)(Oh + idx1) = h1;
        *(__half2*)(Ol + idx1) = lo1;
    }
#undef LOADKV
}

// ---------------------------------------------------------------------------
// Launch
// ---------------------------------------------------------------------------
extern "C" void kernel_launch(void* const* d_in, const int* in_sizes, int n_in,
                              void* d_out, int out_size)
{
    const float* x    = (const float*)d_in[0];
    const float* cosb = (const float*)d_in[1];
    const float* sinb = (const float*)d_in[2];
    const float* Wq   = (const float*)d_in[3];
    const float* bq   = (const float*)d_in[4];
    const float* Wk   = (const float*)d_in[5];
    const float* bk   = (const float*)d_in[6];
    const float* Wv   = (const float*)d_in[7];
    const float* bv   = (const float*)d_in[8];
    const float* qnw  = (const float*)d_in[9];
    const float* knw  = (const float*)d_in[10];
    const float* Wo   = (const float*)d_in[11];
    const float* bo   = (const float*)d_in[12];
    float* out = (float*)d_out;

    float *qp, *kp;
    cudaGetSymbolAddress((void**)&qp, g_q);
    cudaGetSymbolAddress((void**)&kp, g_k);
    __half *xh, *xl, *qhp, *qlp, *k16, *v16, *ohp, *olp;
    __half *wq16, *wk16, *wv16, *wo16;
    cudaGetSymbolAddress((void**)&xh, g_xh);    cudaGetSymbolAddress((void**)&xl, g_xl);
    cudaGetSymbolAddress((void**)&qhp, g_qh);   cudaGetSymbolAddress((void**)&qlp, g_ql);
    cudaGetSymbolAddress((void**)&k16, g_k16);  cudaGetSymbolAddress((void**)&v16, g_v16);
    cudaGetSymbolAddress((void**)&ohp, g_oh);   cudaGetSymbolAddress((void**)&olp, g_ol);
    cudaGetSymbolAddress((void**)&wq16, g_wq16); cudaGetSymbolAddress((void**)&wk16, g_wk16);
    cudaGetSymbolAddress((void**)&wv16, g_wv16); cudaGetSymbolAddress((void**)&wo16, g_wo16);

    const int nx4 = M_ * D_ / 4;
    const int nw4 = D_ * D_ / 4;
    split_f16<<<nx4 / 256, 256>>>((const float4*)x,  (__half2*)xh,   (__half2*)xl, nx4);
    split_f16<<<nw4 / 256, 256>>>((const float4*)Wq, (__half2*)wq16, nullptr, nw4);
    split_f16<<<nw4 / 256, 256>>>((const float4*)Wk, (__half2*)wk16, nullptr, nw4);
    split_f16<<<nw4 / 256, 256>>>((const float4*)Wv, (__half2*)wv16, nullptr, nw4);
    split_f16<<<nw4 / 256, 256>>>((const float4*)Wo, (__half2*)wo16, nullptr, nw4);

    cudaFuncSetAttribute(gemm_f16_2p, cudaFuncAttributeMaxDynamicSharedMemorySize, GEMM_SMEM);
    dim3 ggrid(D_ / 256, M_ / 128);   // (8, 32)
    gemm_f16_2p<<<ggrid, 256, GEMM_SMEM>>>(xh, xl, wq16, bq, qp, nullptr, M_, D_, D_);
    gemm_f16_2p<<<ggrid, 256, GEMM_SMEM>>>(xh, xl, wk16, bk, kp, nullptr, M_, D_, D_);
    gemm_f16_2p<<<ggrid, 256, GEMM_SMEM>>>(xh, xl, wv16, bv, nullptr, v16, M_, D_, D_);

    rmsnorm_rope_f16<<<M_, 256>>>(qp, qnw, cosb, sinb, qhp, qlp);
    rmsnorm_rope_f16<<<M_, 256>>>(kp, knw, cosb, sinb, k16, nullptr);

    cudaFuncSetAttribute(flash_attn_f16, cudaFuncAttributeMaxDynamicSharedMemorySize, 2 * FA_STAGE);
    flash_attn_f16<<<dim3(T_ / 64, H_, B_), 128, 2 * FA_STAGE>>>(qhp, qlp, k16, v16, ohp, olp);

    gemm_f16_2p<<<ggrid, 256, GEMM_SMEM>>>(ohp, olp, wo16, bo, out, nullptr, M_, D_, D_);
}